// round 1
// baseline (speedup 1.0000x reference)
#include <cuda_runtime.h>
#include <cuda_bf16.h>
#include <cstdint>

#define DIM      1024
#define D_INNER  2048
#define NHEADS   16
#define HEADDIM  128
#define D_STATE  64
#define D_PROJ   4240   // 2*D_INNER + 2*D_STATE + NHEADS
#define B_SZ     8
#define T_SZ     1024
#define M_TOK    (B_SZ * T_SZ)   // 8192

// Scratch (no cudaMalloc allowed): device globals.
__device__ float g_proj[(size_t)M_TOK * D_PROJ];   // 139 MB
__device__ float g_ys[(size_t)M_TOK * D_INNER];    // 67 MB

// ---------------------------------------------------------------------------
// fp32 tiled GEMM, "NT" form: C[m,n] = sum_k A[m,k] * W[n,k]
// A: [M,K] row-major, W: [N,K] row-major, C: [M,N] row-major.
// BM=BN=128, BK=8, 256 threads, 8x8 per-thread microtile.
// M must be a multiple of 128 (it is: 8192). N,K arbitrary-ish (K%8==0).
// ---------------------------------------------------------------------------
__global__ void __launch_bounds__(256, 2)
sgemm_nt(const float* __restrict__ A, const float* __restrict__ W,
         float* __restrict__ C, int M, int N, int K)
{
    __shared__ float sA[8][128];
    __shared__ float sW[8][128];

    const int tid = threadIdx.x;
    const int bm  = blockIdx.y * 128;
    const int bn  = blockIdx.x * 128;

    // microtile coords
    const int rm = (tid / 16) * 8;
    const int rn = (tid % 16) * 8;

    // load coords: each thread fetches one float4 of A and one of W per k-step
    const int ldRow = tid >> 1;          // 0..127
    const int ldK4  = (tid & 1) * 4;     // 0 or 4

    const float* aPtr = A + (size_t)(bm + ldRow) * K + ldK4;
    const bool   wValid = (bn + ldRow) < N;
    const int    wRow   = wValid ? (bn + ldRow) : (N - 1);
    const float* wPtr   = W + (size_t)wRow * K + ldK4;

    float acc[8][8];
#pragma unroll
    for (int i = 0; i < 8; i++)
#pragma unroll
        for (int j = 0; j < 8; j++) acc[i][j] = 0.f;

    for (int k0 = 0; k0 < K; k0 += 8) {
        float4 av = *(const float4*)(aPtr + k0);
        float4 wv;
        if (wValid) wv = *(const float4*)(wPtr + k0);
        else        wv = make_float4(0.f, 0.f, 0.f, 0.f);

        sA[ldK4 + 0][ldRow] = av.x;
        sA[ldK4 + 1][ldRow] = av.y;
        sA[ldK4 + 2][ldRow] = av.z;
        sA[ldK4 + 3][ldRow] = av.w;
        sW[ldK4 + 0][ldRow] = wv.x;
        sW[ldK4 + 1][ldRow] = wv.y;
        sW[ldK4 + 2][ldRow] = wv.z;
        sW[ldK4 + 3][ldRow] = wv.w;
        __syncthreads();

#pragma unroll
        for (int k = 0; k < 8; k++) {
            float a[8], w[8];
            float4 a0 = *(const float4*)&sA[k][rm];
            float4 a1 = *(const float4*)&sA[k][rm + 4];
            float4 w0 = *(const float4*)&sW[k][rn];
            float4 w1 = *(const float4*)&sW[k][rn + 4];
            a[0]=a0.x; a[1]=a0.y; a[2]=a0.z; a[3]=a0.w;
            a[4]=a1.x; a[5]=a1.y; a[6]=a1.z; a[7]=a1.w;
            w[0]=w0.x; w[1]=w0.y; w[2]=w0.z; w[3]=w0.w;
            w[4]=w1.x; w[5]=w1.y; w[6]=w1.z; w[7]=w1.w;
#pragma unroll
            for (int i = 0; i < 8; i++)
#pragma unroll
                for (int j = 0; j < 8; j++)
                    acc[i][j] += a[i] * w[j];
        }
        __syncthreads();
    }

    // store (M always in-bounds; guard N)
#pragma unroll
    for (int i = 0; i < 8; i++) {
        const int row = bm + rm + i;
        float* crow = C + (size_t)row * N + bn + rn;
#pragma unroll
        for (int j = 0; j < 8; j++) {
            if (bn + rn + j < N) crow[j] = acc[i][j];
        }
    }
}

// ---------------------------------------------------------------------------
// Sequential scan: one block per (b, h). 128 threads; thread p owns H[p, 0:64]
// in registers. Per step: H = dec*H + silu(x)*B ; y = H . C ;
// out = y * silu(z + y). B/C tiles double-buffered in shared.
// ---------------------------------------------------------------------------
__global__ void __launch_bounds__(128)
scan_kernel(const float* __restrict__ H0, const float* __restrict__ dt_bias,
            float* __restrict__ ys, float* __restrict__ Hout, int writeH)
{
    const int bh = blockIdx.x;
    const int b  = bh >> 4;
    const int h  = bh & 15;
    const int p  = threadIdx.x;   // 0..127

    float H[64];
    const float* h0p = H0 + (((size_t)(b * NHEADS + h) * HEADDIM) + p) * D_STATE;
#pragma unroll
    for (int n = 0; n < 64; n++) H[n] = h0p[n];

    const float dtb = dt_bias[h];
    const float* projb = g_proj + (size_t)(b * T_SZ) * D_PROJ;

    __shared__ float sB[2][64];
    __shared__ float sC[2][64];

    // preload t = 0
    if (p < 64) sB[0][p]      = projb[2 * D_INNER + p];
    else        sC[0][p - 64] = projb[2 * D_INNER + 64 + (p - 64)];
    __syncthreads();

    for (int t = 0; t < T_SZ; t++) {
        const float* row = projb + (size_t)t * D_PROJ;
        const int cb = t & 1;
        const int nb = cb ^ 1;

        // per-thread scalars (prefetch-ish: issued before the FMA block)
        float xv = row[h * HEADDIM + p];
        float zv = row[D_INNER + h * HEADDIM + p];
        float dt = row[2 * D_INNER + 2 * D_STATE + h];

        // prefetch next step's B/C into the other buffer
        if (t + 1 < T_SZ) {
            const float* nrow = row + D_PROJ;
            if (p < 64) sB[nb][p]      = nrow[2 * D_INNER + p];
            else        sC[nb][p - 64] = nrow[2 * D_INNER + 64 + (p - 64)];
        }

        const float dec = 1.f / (1.f + __expf(-(dt + dtb)));
        const float xs  = xv / (1.f + __expf(-xv));          // silu(x)

        float y0 = 0.f, y1 = 0.f, y2 = 0.f, y3 = 0.f;
#pragma unroll
        for (int n = 0; n < 64; n += 4) {
            H[n + 0] = dec * H[n + 0] + xs * sB[cb][n + 0];
            y0 += H[n + 0] * sC[cb][n + 0];
            H[n + 1] = dec * H[n + 1] + xs * sB[cb][n + 1];
            y1 += H[n + 1] * sC[cb][n + 1];
            H[n + 2] = dec * H[n + 2] + xs * sB[cb][n + 2];
            y2 += H[n + 2] * sC[cb][n + 2];
            H[n + 3] = dec * H[n + 3] + xs * sB[cb][n + 3];
            y3 += H[n + 3] * sC[cb][n + 3];
        }
        const float y  = (y0 + y1) + (y2 + y3);
        const float zy = zv + y;
        const float out = y * (zy / (1.f + __expf(-zy)));    // y * silu(z + y)

        ys[(size_t)(b * T_SZ + t) * D_INNER + h * HEADDIM + p] = out;

        __syncthreads();   // buffer handoff
    }

    if (writeH) {
        float* hp = Hout + (((size_t)(b * NHEADS + h) * HEADDIM) + p) * D_STATE;
#pragma unroll
        for (int n = 0; n < 64; n++) hp[n] = H[n];
    }
}

// ---------------------------------------------------------------------------
extern "C" void kernel_launch(void* const* d_in, const int* in_sizes, int n_in,
                              void* d_out, int out_size)
{
    const float* x       = (const float*)d_in[0];
    const float* H0      = (const float*)d_in[1];
    const float* W_in    = (const float*)d_in[2];
    const float* W_out   = (const float*)d_in[3];
    const float* dt_bias = (const float*)d_in[4];
    float* out = (float*)d_out;

    static float* proj_ptr = nullptr;
    static float* ys_ptr   = nullptr;
    if (!proj_ptr) {
        cudaGetSymbolAddress((void**)&proj_ptr, g_proj);
        cudaGetSymbolAddress((void**)&ys_ptr, g_ys);
    }

    const int out_elems = B_SZ * T_SZ * DIM;                        // 8388608
    const int h_elems   = B_SZ * NHEADS * HEADDIM * D_STATE;        // 1048576
    const int writeH    = (out_size >= out_elems + h_elems) ? 1 : 0;
    float* Hout = out + out_elems;

    // 1) proj = x @ W_in^T   [8192, 4240]
    {
        dim3 grid((D_PROJ + 127) / 128, M_TOK / 128);
        sgemm_nt<<<grid, 256>>>(x, W_in, proj_ptr, M_TOK, D_PROJ, DIM);
    }
    // 2) sequential scan -> ys [8192, 2048] (+ H_final)
    {
        scan_kernel<<<B_SZ * NHEADS, 128>>>(H0, dt_bias, ys_ptr, Hout, writeH);
    }
    // 3) output = ys @ W_out^T   [8192, 1024] -> d_out (already [B,T,DIM] layout)
    {
        dim3 grid(DIM / 128, M_TOK / 128);
        sgemm_nt<<<grid, 256>>>(ys_ptr, W_out, out, M_TOK, DIM, D_INNER);
    }
}

// round 2
// speedup vs baseline: 1.1892x; 1.1892x over previous
#include <cuda_runtime.h>
#include <cuda_bf16.h>
#include <cstdint>

#define DIM      1024
#define D_INNER  2048
#define NHEADS   16
#define HEADDIM  128
#define D_STATE  64
#define D_PROJ   4240   // 2*D_INNER + 2*D_STATE + NHEADS
#define B_SZ     8
#define T_SZ     1024
#define M_TOK    (B_SZ * T_SZ)   // 8192

// Scratch (no cudaMalloc allowed): device globals.
__device__ float g_proj[(size_t)M_TOK * D_PROJ];   // 139 MB
__device__ float g_ys[(size_t)M_TOK * D_INNER];    // 67 MB

// ---------------------------------------------------------------------------
// fp32 tiled GEMM, "NT" form: C[m,n] = sum_k A[m,k] * W[n,k]
// A: [M,K] row-major, W: [N,K] row-major, C: [M,N] row-major.
// BM=BN=128, BK=16, 256 threads, 8x8 microtile, double-buffered smem with
// register-staged global prefetch. M % 128 == 0, K % 16 == 0. N guarded.
// ---------------------------------------------------------------------------
#define STORE_TILE(buf)                               \
    do {                                              \
        sA[buf][ldK + 0][ldRow] = a0v.x;              \
        sA[buf][ldK + 1][ldRow] = a0v.y;              \
        sA[buf][ldK + 2][ldRow] = a0v.z;              \
        sA[buf][ldK + 3][ldRow] = a0v.w;              \
        sA[buf][ldK + 8][ldRow] = a1v.x;              \
        sA[buf][ldK + 9][ldRow] = a1v.y;              \
        sA[buf][ldK +10][ldRow] = a1v.z;              \
        sA[buf][ldK +11][ldRow] = a1v.w;              \
        sW[buf][ldK + 0][ldRow] = w0v.x;              \
        sW[buf][ldK + 1][ldRow] = w0v.y;              \
        sW[buf][ldK + 2][ldRow] = w0v.z;              \
        sW[buf][ldK + 3][ldRow] = w0v.w;              \
        sW[buf][ldK + 8][ldRow] = w1v.x;              \
        sW[buf][ldK + 9][ldRow] = w1v.y;              \
        sW[buf][ldK +10][ldRow] = w1v.z;              \
        sW[buf][ldK +11][ldRow] = w1v.w;              \
    } while (0)

__global__ void __launch_bounds__(256, 2)
sgemm_nt(const float* __restrict__ A, const float* __restrict__ W,
         float* __restrict__ C, int M, int N, int K)
{
    __shared__ float sA[2][16][128];
    __shared__ float sW[2][16][128];

    const int tid = threadIdx.x;
    const int bm  = blockIdx.y * 128;
    const int bn  = blockIdx.x * 128;

    // microtile coords
    const int rm = (tid / 16) * 8;
    const int rn = (tid % 16) * 8;

    // load coords: each thread fetches two float4 of A and two of W per tile
    const int ldRow = tid >> 1;          // 0..127
    const int ldK   = (tid & 1) * 4;     // 0 or 4

    const float* aPtr = A + (size_t)(bm + ldRow) * K + ldK;
    // clamp invalid W rows to row N-1 (garbage columns are masked at store)
    const int wRow = (bn + ldRow) < N ? (bn + ldRow) : (N - 1);
    const float* wPtr = W + (size_t)wRow * K + ldK;

    float4 a0v, a1v, w0v, w1v;
    a0v = *(const float4*)(aPtr);
    a1v = *(const float4*)(aPtr + 8);
    w0v = *(const float4*)(wPtr);
    w1v = *(const float4*)(wPtr + 8);

    float acc[8][8];
#pragma unroll
    for (int i = 0; i < 8; i++)
#pragma unroll
        for (int j = 0; j < 8; j++) acc[i][j] = 0.f;

    STORE_TILE(0);
    __syncthreads();

    const int nk = K >> 4;
    for (int kt = 0; kt < nk; kt++) {
        const int buf = kt & 1;

        // prefetch next tile into registers (overlaps with compute below)
        if (kt + 1 < nk) {
            const float* ap = aPtr + (size_t)(kt + 1) * 16;
            const float* wp = wPtr + (size_t)(kt + 1) * 16;
            a0v = *(const float4*)(ap);
            a1v = *(const float4*)(ap + 8);
            w0v = *(const float4*)(wp);
            w1v = *(const float4*)(wp + 8);
        }

#pragma unroll
        for (int k = 0; k < 16; k++) {
            float a[8], w[8];
            float4 t0 = *(const float4*)&sA[buf][k][rm];
            float4 t1 = *(const float4*)&sA[buf][k][rm + 4];
            float4 t2 = *(const float4*)&sW[buf][k][rn];
            float4 t3 = *(const float4*)&sW[buf][k][rn + 4];
            a[0]=t0.x; a[1]=t0.y; a[2]=t0.z; a[3]=t0.w;
            a[4]=t1.x; a[5]=t1.y; a[6]=t1.z; a[7]=t1.w;
            w[0]=t2.x; w[1]=t2.y; w[2]=t2.z; w[3]=t2.w;
            w[4]=t3.x; w[5]=t3.y; w[6]=t3.z; w[7]=t3.w;
#pragma unroll
            for (int i = 0; i < 8; i++)
#pragma unroll
                for (int j = 0; j < 8; j++)
                    acc[i][j] += a[i] * w[j];
        }

        if (kt + 1 < nk) {
            STORE_TILE(buf ^ 1);
        }
        __syncthreads();
    }

    // store (M always in-bounds; guard N)
    const bool fullN = (bn + 128) <= N;
#pragma unroll
    for (int i = 0; i < 8; i++) {
        const int row = bm + rm + i;
        float* crow = C + (size_t)row * N + bn + rn;
        if (fullN) {
            *(float4*)(crow)     = make_float4(acc[i][0], acc[i][1], acc[i][2], acc[i][3]);
            *(float4*)(crow + 4) = make_float4(acc[i][4], acc[i][5], acc[i][6], acc[i][7]);
        } else {
#pragma unroll
            for (int j = 0; j < 8; j++)
                if (bn + rn + j < N) crow[j] = acc[i][j];
        }
    }
}

// ---------------------------------------------------------------------------
// Sequential scan: one block per (b, h). 128 threads; thread p owns H[p, 0:64]
// in registers. Latency-pipelined:
//   - B/C tiles prefetched 3 steps ahead into a 4-deep smem ring
//   - x/z/dt prefetched 2 steps ahead into registers
// One __syncthreads per step (ring-buffer handoff).
// ---------------------------------------------------------------------------
__global__ void __launch_bounds__(128)
scan_kernel(const float* __restrict__ H0, const float* __restrict__ dt_bias,
            float* __restrict__ ys, float* __restrict__ Hout, int writeH)
{
    const int bh = blockIdx.x;
    const int b  = bh >> 4;
    const int h  = bh & 15;
    const int p  = threadIdx.x;   // 0..127

    float H[64];
    const float* h0p = H0 + (((size_t)(b * NHEADS + h) * HEADDIM) + p) * D_STATE;
#pragma unroll
    for (int n = 0; n < 64; n++) H[n] = h0p[n];

    const float dtb = dt_bias[h];
    const float* projb = g_proj + (size_t)(b * T_SZ) * D_PROJ;

    __shared__ float sB[4][64];
    __shared__ float sC[4][64];

    // preload B/C for t = 0,1,2
#pragma unroll
    for (int tt = 0; tt < 3; tt++) {
        const float* r = projb + (size_t)tt * D_PROJ + 2 * D_INNER;
        if (p < 64) sB[tt][p]      = r[p];
        else        sC[tt][p - 64] = r[p];
    }

    const int xoff = h * HEADDIM + p;
    const int zoff = D_INNER + h * HEADDIM + p;
    const int doff = 2 * D_INNER + 2 * D_STATE + h;

    // register pipeline for x/z/dt (depth 2)
    float xv_c = projb[xoff];
    float zv_c = projb[zoff];
    float dt_c = projb[doff];
    float xv_n = projb[D_PROJ + xoff];
    float zv_n = projb[D_PROJ + zoff];
    float dt_n = projb[D_PROJ + doff];
    __syncthreads();

    float* ysp = ys + (size_t)(b * T_SZ) * D_INNER + h * HEADDIM + p;

    for (int t = 0; t < T_SZ; t++) {
        // prefetch B/C for t+3 into ring slot (t+3)&3 (last read at iter t-1,
        // protected by the sync at the end of iter t-1)
        if (t + 3 < T_SZ) {
            const float* r = projb + (size_t)(t + 3) * D_PROJ + 2 * D_INNER;
            if (p < 64) sB[(t + 3) & 3][p]      = r[p];
            else        sC[(t + 3) & 3][p - 64] = r[p];
        }
        // prefetch x/z/dt for t+2
        float xv2 = 0.f, zv2 = 0.f, dt2 = 0.f;
        if (t + 2 < T_SZ) {
            const float* r2 = projb + (size_t)(t + 2) * D_PROJ;
            xv2 = r2[xoff];
            zv2 = r2[zoff];
            dt2 = r2[doff];
        }

        const float dec = 1.f / (1.f + __expf(-(dt_c + dtb)));
        const float xs  = xv_c / (1.f + __expf(-xv_c));     // silu(x)

        const float* Bc = sB[t & 3];
        const float* Cc = sC[t & 3];

        float y0 = 0.f, y1 = 0.f, y2 = 0.f, y3 = 0.f;
#pragma unroll
        for (int n = 0; n < 64; n += 8) {
            float4 bA = *(const float4*)&Bc[n];
            float4 bB = *(const float4*)&Bc[n + 4];
            float4 cA = *(const float4*)&Cc[n];
            float4 cB = *(const float4*)&Cc[n + 4];
            H[n + 0] = dec * H[n + 0] + xs * bA.x;  y0 += H[n + 0] * cA.x;
            H[n + 1] = dec * H[n + 1] + xs * bA.y;  y1 += H[n + 1] * cA.y;
            H[n + 2] = dec * H[n + 2] + xs * bA.z;  y2 += H[n + 2] * cA.z;
            H[n + 3] = dec * H[n + 3] + xs * bA.w;  y3 += H[n + 3] * cA.w;
            H[n + 4] = dec * H[n + 4] + xs * bB.x;  y0 += H[n + 4] * cB.x;
            H[n + 5] = dec * H[n + 5] + xs * bB.y;  y1 += H[n + 5] * cB.y;
            H[n + 6] = dec * H[n + 6] + xs * bB.z;  y2 += H[n + 6] * cB.z;
            H[n + 7] = dec * H[n + 7] + xs * bB.w;  y3 += H[n + 7] * cB.w;
        }
        const float y  = (y0 + y1) + (y2 + y3);
        const float zy = zv_c + y;
        ysp[(size_t)t * D_INNER] = y * (zy / (1.f + __expf(-zy)));   // y*silu(z+y)

        // rotate register pipeline
        xv_c = xv_n; zv_c = zv_n; dt_c = dt_n;
        xv_n = xv2;  zv_n = zv2;  dt_n = dt2;

        __syncthreads();   // ring handoff
    }

    if (writeH) {
        float* hp = Hout + (((size_t)(b * NHEADS + h) * HEADDIM) + p) * D_STATE;
#pragma unroll
        for (int n = 0; n < 64; n++) hp[n] = H[n];
    }
}

// ---------------------------------------------------------------------------
extern "C" void kernel_launch(void* const* d_in, const int* in_sizes, int n_in,
                              void* d_out, int out_size)
{
    const float* x       = (const float*)d_in[0];
    const float* H0      = (const float*)d_in[1];
    const float* W_in    = (const float*)d_in[2];
    const float* W_out   = (const float*)d_in[3];
    const float* dt_bias = (const float*)d_in[4];
    float* out = (float*)d_out;

    static float* proj_ptr = nullptr;
    static float* ys_ptr   = nullptr;
    if (!proj_ptr) {
        cudaGetSymbolAddress((void**)&proj_ptr, g_proj);
        cudaGetSymbolAddress((void**)&ys_ptr, g_ys);
    }

    const int out_elems = B_SZ * T_SZ * DIM;                        // 8388608
    const int h_elems   = B_SZ * NHEADS * HEADDIM * D_STATE;        // 1048576
    const int writeH    = (out_size >= out_elems + h_elems) ? 1 : 0;
    float* Hout = out + out_elems;

    // 1) proj = x @ W_in^T   [8192, 4240]
    {
        dim3 grid((D_PROJ + 127) / 128, M_TOK / 128);
        sgemm_nt<<<grid, 256>>>(x, W_in, proj_ptr, M_TOK, D_PROJ, DIM);
    }
    // 2) sequential scan -> ys [8192, 2048] (+ H_final)
    {
        scan_kernel<<<B_SZ * NHEADS, 128>>>(H0, dt_bias, ys_ptr, Hout, writeH);
    }
    // 3) output = ys @ W_out^T   [8192, 1024] -> d_out (already [B,T,DIM] layout)
    {
        dim3 grid(DIM / 128, M_TOK / 128);
        sgemm_nt<<<grid, 256>>>(ys_ptr, W_out, out, M_TOK, DIM, D_INNER);
    }
}

// round 4
// speedup vs baseline: 2.0062x; 1.6870x over previous
#include <cuda_runtime.h>
#include <cuda_bf16.h>
#include <cstdint>

#define DIM      1024
#define D_INNER  2048
#define NHEADS   16
#define HEADDIM  128
#define D_STATE  64
#define D_PROJ   4240   // 2*D_INNER + 2*D_STATE + NHEADS
#define B_SZ     8
#define T_SZ     1024
#define M_TOK    (B_SZ * T_SZ)   // 8192

// ---------------------------------------------------------------------------
// Scratch (no cudaMalloc allowed): device globals.
// ---------------------------------------------------------------------------
__device__ float g_proj[(size_t)M_TOK * D_PROJ];          // 139 MB
__device__ float g_ys[(size_t)M_TOK * D_INNER];           // 67 MB (tf32-rounded)
__device__ float g_xr[(size_t)M_TOK * DIM];               // 33 MB  x rounded
__device__ float g_wir[(size_t)D_PROJ * DIM];             // 17 MB  W_in rounded
__device__ float g_wor[(size_t)DIM * D_INNER];            // 8  MB  W_out rounded
__device__ float g_xst[(size_t)M_TOK * D_INNER];          // 67 MB  silu(x_p), [b,h,t,p]
__device__ float g_zt [(size_t)M_TOK * D_INNER];          // 67 MB  z, [b,h,t,p]
__device__ float g_Bc [(size_t)B_SZ * T_SZ * D_STATE];    // 2 MB   [b,t,n]
__device__ float g_Cc [(size_t)B_SZ * T_SZ * D_STATE];    // 2 MB
__device__ float g_dec[(size_t)B_SZ * T_SZ * NHEADS];     // 0.5 MB sigmoid(dt+bias)

// ---------------------------------------------------------------------------
// helpers
// ---------------------------------------------------------------------------
__device__ __forceinline__ uint32_t f2tf32(float f) {
    uint32_t u;
    asm("cvt.rna.tf32.f32 %0, %1;" : "=r"(u) : "f"(f));
    return u;
}

__device__ __forceinline__ void cpasync16(uint32_t dst, const void* src) {
    asm volatile("cp.async.cg.shared.global [%0], [%1], 16;" :: "r"(dst), "l"(src));
}

__device__ __forceinline__ void mma_tf32(float* c, const uint32_t* a,
                                         uint32_t b0, uint32_t b1) {
    asm volatile(
        "mma.sync.aligned.m16n8k8.row.col.f32.tf32.tf32.f32 "
        "{%0,%1,%2,%3}, {%4,%5,%6,%7}, {%8,%9}, {%0,%1,%2,%3};"
        : "+f"(c[0]), "+f"(c[1]), "+f"(c[2]), "+f"(c[3])
        : "r"(a[0]), "r"(a[1]), "r"(a[2]), "r"(a[3]), "r"(b0), "r"(b1));
}

// ---------------------------------------------------------------------------
// round fp32 -> tf32-bits (stored as fp32)
// ---------------------------------------------------------------------------
__global__ void round_tf32(const float* __restrict__ src, float* __restrict__ dst, int n) {
    for (int i = blockIdx.x * blockDim.x + threadIdx.x; i < n;
         i += gridDim.x * blockDim.x)
        dst[i] = __uint_as_float(f2tf32(src[i]));
}

// ---------------------------------------------------------------------------
// tf32 tensor-core GEMM, NT form: C[m,n] = sum_k A[m,k] * W[n,k]
// Inputs must already be tf32-rounded. BM=BN=128, BK=32, 256 threads (8 warps),
// each warp owns a 64x32 output tile (2x4 warp grid). cp.async double buffer.
// Smem k-major with 16B-chunk XOR swizzle; conflict-free LDS.32 fragments.
// M % 128 == 0, K % 32 == 0; N guarded.
// ---------------------------------------------------------------------------
__global__ void __launch_bounds__(256)
gemm_tf32(const float* __restrict__ A, const float* __restrict__ W,
          float* __restrict__ C, int M, int N, int K)
{
    extern __shared__ float smem[];   // [2][8192] floats: A 4096 + B 4096 per buf
    const uint32_t smemAddr = (uint32_t)__cvta_generic_to_shared(smem);

    const int tid  = threadIdx.x;
    const int lane = tid & 31;
    const int wid  = tid >> 5;        // 0..7
    const int wm   = wid & 1;         // m-group (64 rows)
    const int wn   = wid >> 1;        // n-group (32 cols)

    const int bm = blockIdx.y * 128;
    const int bn = blockIdx.x * 128;

    // staging coords
    const int sr   = tid >> 1;        // 0..127 tile row
    const int half = tid & 1;         // 4 chunks each
    const float* arow = A + (size_t)(bm + sr) * K;
    const int wRow = (bn + sr) < N ? (bn + sr) : (N - 1);
    const float* wrow = W + (size_t)wRow * K;

    // fragment addressing constants (float-index units)
    int cx[8];
#pragma unroll
    for (int j = 0; j < 8; j++)
        cx[j] = ((j ^ (lane >> 2)) << 2) + (lane & 3);
    int rA[4], rB[4];
#pragma unroll
    for (int mt = 0; mt < 4; mt++)
        rA[mt] = (wm * 64 + mt * 16 + (lane >> 2)) * 32;
#pragma unroll
    for (int nt = 0; nt < 4; nt++)
        rB[nt] = (wn * 32 + nt * 8 + (lane >> 2)) * 32;

    float acc[4][4][4];
#pragma unroll
    for (int mt = 0; mt < 4; mt++)
#pragma unroll
        for (int nt = 0; nt < 4; nt++)
#pragma unroll
            for (int r = 0; r < 4; r++) acc[mt][nt][r] = 0.f;

    const int nk = K >> 5;

    // stage helper (macro to keep cp.async addresses simple)
#define STAGE(bufIdx, kk)                                                     \
    do {                                                                      \
        uint32_t baseA = smemAddr + (bufIdx) * 32768 + sr * 128;              \
        uint32_t baseB = baseA + 16384;                                       \
        _Pragma("unroll")                                                     \
        for (int i = 0; i < 4; i++) {                                         \
            int ch  = half * 4 + i;                                           \
            int chs = ch ^ (sr & 7);                                          \
            cpasync16(baseA + chs * 16, arow + (kk) + ch * 4);                \
            cpasync16(baseB + chs * 16, wrow + (kk) + ch * 4);                \
        }                                                                     \
    } while (0)

    STAGE(0, 0);
    asm volatile("cp.async.commit_group;");

    for (int kt = 0; kt < nk; kt++) {
        const int buf = kt & 1;
        if (kt + 1 < nk) {
            STAGE(buf ^ 1, (kt + 1) * 32);
            asm volatile("cp.async.commit_group;");
            asm volatile("cp.async.wait_group 1;");
        } else {
            asm volatile("cp.async.wait_group 0;");
        }
        __syncthreads();

        const uint32_t* sAu = reinterpret_cast<const uint32_t*>(smem) + buf * 8192;
        const uint32_t* sBu = sAu + 4096;

#pragma unroll
        for (int ks = 0; ks < 4; ks++) {
            uint32_t bf[4][2];
#pragma unroll
            for (int nt = 0; nt < 4; nt++) {
                bf[nt][0] = sBu[rB[nt] + cx[2 * ks]];
                bf[nt][1] = sBu[rB[nt] + cx[2 * ks + 1]];
            }
            uint32_t af[4][4];
#pragma unroll
            for (int mt = 0; mt < 4; mt++) {
                af[mt][0] = sAu[rA[mt] + cx[2 * ks]];
                af[mt][1] = sAu[rA[mt] + 256 + cx[2 * ks]];
                af[mt][2] = sAu[rA[mt] + cx[2 * ks + 1]];
                af[mt][3] = sAu[rA[mt] + 256 + cx[2 * ks + 1]];
            }
#pragma unroll
            for (int mt = 0; mt < 4; mt++)
#pragma unroll
                for (int nt = 0; nt < 4; nt++)
                    mma_tf32(acc[mt][nt], af[nt == 0 ? mt : mt], bf[nt][0], bf[nt][1]);
        }
        __syncthreads();
    }
#undef STAGE

    // epilogue: c0,c1 -> (row, col..col+1); c2,c3 -> (row+8, col..col+1)
#pragma unroll
    for (int mt = 0; mt < 4; mt++) {
        const int row0 = bm + wm * 64 + mt * 16 + (lane >> 2);
#pragma unroll
        for (int nt = 0; nt < 4; nt++) {
            const int col = bn + wn * 32 + nt * 8 + (lane & 3) * 2;
            if (col < N) {
                float2* p0 = (float2*)(C + (size_t)row0 * N + col);
                float2* p1 = (float2*)(C + (size_t)(row0 + 8) * N + col);
                *p0 = make_float2(acc[mt][nt][0], acc[mt][nt][1]);
                *p1 = make_float2(acc[mt][nt][2], acc[mt][nt][3]);
            }
        }
    }
}

// ---------------------------------------------------------------------------
// prep: reshape proj into scan-friendly sequential streams.
// grid = B*T blocks (one per (b,t) token), 256 threads.
//   xs[b,h,t,p] = silu(x_p), z[b,h,t,p], Bc/Cc[b,t,n], dec[b,t,h]
// ---------------------------------------------------------------------------
__global__ void __launch_bounds__(256)
prep_kernel(const float* __restrict__ dt_bias)
{
    const int bt = blockIdx.x;
    const int b  = bt >> 10;
    const int t  = bt & 1023;
    const int tid = threadIdx.x;
    const float* row = g_proj + (size_t)bt * D_PROJ;

#pragma unroll
    for (int i = tid; i < D_INNER; i += 256) {
        const int h = i >> 7;
        const int p = i & 127;
        const size_t idx = ((size_t)(b * NHEADS + h) * T_SZ + t) * HEADDIM + p;
        const float xv = row[i];
        g_xst[idx] = xv / (1.f + __expf(-xv));
        g_zt[idx]  = row[D_INNER + i];
    }
    if (tid < D_STATE) {
        g_Bc[(size_t)bt * D_STATE + tid] = row[2 * D_INNER + tid];
        g_Cc[(size_t)bt * D_STATE + tid] = row[2 * D_INNER + D_STATE + tid];
    } else if (tid >= 64 && tid < 64 + NHEADS) {
        const int h = tid - 64;
        const float dt = row[2 * D_INNER + 2 * D_STATE + h];
        g_dec[(size_t)bt * NHEADS + h] = 1.f / (1.f + __expf(-(dt + dt_bias[h])));
    }
}

// ---------------------------------------------------------------------------
// scan: one block per (b,h), 128 threads; thread p owns H[p,0:64] in regs.
// All inputs are sequential streams. B/C via 4-deep smem ring (prefetch t+3),
// xs/z/dec via depth-2 register pipeline. ys written tf32-rounded.
// ---------------------------------------------------------------------------
__global__ void __launch_bounds__(128)
scan_kernel(const float* __restrict__ H0, float* __restrict__ ys,
            float* __restrict__ Hout, int writeH)
{
    const int bh = blockIdx.x;
    const int b  = bh >> 4;
    const int h  = bh & 15;
    const int p  = threadIdx.x;

    float H[64];
    const float* h0p = H0 + (((size_t)bh * HEADDIM) + p) * D_STATE;
#pragma unroll
    for (int n = 0; n < 64; n++) H[n] = h0p[n];

    const float* xsp  = g_xst + (size_t)bh * T_SZ * HEADDIM + p;
    const float* zp   = g_zt  + (size_t)bh * T_SZ * HEADDIM + p;
    const float* decp = g_dec + (size_t)b * T_SZ * NHEADS + h;
    const float* Bcb  = g_Bc + (size_t)b * T_SZ * D_STATE;
    const float* Ccb  = g_Cc + (size_t)b * T_SZ * D_STATE;

    __shared__ float sB[4][64];
    __shared__ float sC[4][64];

#pragma unroll
    for (int tt = 0; tt < 3; tt++) {
        if (p < 64) sB[tt][p]      = Bcb[tt * D_STATE + p];
        else        sC[tt][p - 64] = Ccb[tt * D_STATE + (p - 64)];
    }

    // register pipeline depth 2
    float xs_c = xsp[0],        z_c = zp[0],        d_c = decp[0];
    float xs_n = xsp[HEADDIM],  z_n = zp[HEADDIM],  d_n = decp[NHEADS];
    __syncthreads();

    float* ysp = ys + (size_t)(b * T_SZ) * D_INNER + h * HEADDIM + p;

    for (int t = 0; t < T_SZ; t++) {
        if (t + 3 < T_SZ) {
            if (p < 64) sB[(t + 3) & 3][p]      = Bcb[(t + 3) * D_STATE + p];
            else        sC[(t + 3) & 3][p - 64] = Ccb[(t + 3) * D_STATE + (p - 64)];
        }
        float xs2 = 0.f, z2 = 0.f, d2 = 0.f;
        if (t + 2 < T_SZ) {
            xs2 = xsp[(t + 2) * HEADDIM];
            z2  = zp[(t + 2) * HEADDIM];
            d2  = decp[(t + 2) * NHEADS];
        }

        const float dec = d_c;
        const float xs  = xs_c;
        const float* Bc = sB[t & 3];
        const float* Cc = sC[t & 3];

        float y0 = 0.f, y1 = 0.f, y2 = 0.f, y3 = 0.f;
#pragma unroll
        for (int n = 0; n < 64; n += 8) {
            float4 bA = *(const float4*)&Bc[n];
            float4 bB = *(const float4*)&Bc[n + 4];
            float4 cA = *(const float4*)&Cc[n];
            float4 cB = *(const float4*)&Cc[n + 4];
            H[n + 0] = dec * H[n + 0] + xs * bA.x;  y0 += H[n + 0] * cA.x;
            H[n + 1] = dec * H[n + 1] + xs * bA.y;  y1 += H[n + 1] * cA.y;
            H[n + 2] = dec * H[n + 2] + xs * bA.z;  y2 += H[n + 2] * cA.z;
            H[n + 3] = dec * H[n + 3] + xs * bA.w;  y3 += H[n + 3] * cA.w;
            H[n + 4] = dec * H[n + 4] + xs * bB.x;  y0 += H[n + 4] * cB.x;
            H[n + 5] = dec * H[n + 5] + xs * bB.y;  y1 += H[n + 5] * cB.y;
            H[n + 6] = dec * H[n + 6] + xs * bB.z;  y2 += H[n + 6] * cB.z;
            H[n + 7] = dec * H[n + 7] + xs * bB.w;  y3 += H[n + 7] * cB.w;
        }
        const float y  = (y0 + y1) + (y2 + y3);
        const float zy = z_c + y;
        const float ov = y * (zy / (1.f + __expf(-zy)));
        ysp[(size_t)t * D_INNER] = __uint_as_float(f2tf32(ov));  // tf32 for GEMM2

        xs_c = xs_n; z_c = z_n; d_c = d_n;
        xs_n = xs2;  z_n = z2;  d_n = d2;

        __syncthreads();
    }

    if (writeH) {
        float* hp = Hout + (((size_t)bh * HEADDIM) + p) * D_STATE;
#pragma unroll
        for (int n = 0; n < 64; n++) hp[n] = H[n];
    }
}

// ---------------------------------------------------------------------------
extern "C" void kernel_launch(void* const* d_in, const int* in_sizes, int n_in,
                              void* d_out, int out_size)
{
    const float* x       = (const float*)d_in[0];
    const float* H0      = (const float*)d_in[1];
    const float* W_in    = (const float*)d_in[2];
    const float* W_out   = (const float*)d_in[3];
    const float* dt_bias = (const float*)d_in[4];
    float* out = (float*)d_out;

    static float *proj_p = nullptr, *ys_p = nullptr, *xr_p = nullptr,
                 *wir_p = nullptr, *wor_p = nullptr;
    if (!proj_p) {
        cudaGetSymbolAddress((void**)&proj_p, g_proj);
        cudaGetSymbolAddress((void**)&ys_p,   g_ys);
        cudaGetSymbolAddress((void**)&xr_p,   g_xr);
        cudaGetSymbolAddress((void**)&wir_p,  g_wir);
        cudaGetSymbolAddress((void**)&wor_p,  g_wor);
        cudaFuncSetAttribute(gemm_tf32,
                             cudaFuncAttributeMaxDynamicSharedMemorySize, 65536);
    }

    const int out_elems = B_SZ * T_SZ * DIM;
    const int h_elems   = B_SZ * NHEADS * HEADDIM * D_STATE;
    const int writeH    = (out_size >= out_elems + h_elems) ? 1 : 0;
    float* Hout = out + out_elems;

    // 0) tf32-round GEMM inputs
    round_tf32<<<2048, 256>>>(x,     xr_p,  M_TOK * DIM);
    round_tf32<<<2048, 256>>>(W_in,  wir_p, D_PROJ * DIM);
    round_tf32<<<1024, 256>>>(W_out, wor_p, DIM * D_INNER);

    // 1) proj = x @ W_in^T   [8192, 4240]   (tf32 MMA)
    {
        dim3 grid((D_PROJ + 127) / 128, M_TOK / 128);
        gemm_tf32<<<grid, 256, 65536>>>(xr_p, wir_p, proj_p, M_TOK, D_PROJ, DIM);
    }
    // 2) reshape + activations
    prep_kernel<<<B_SZ * T_SZ, 256>>>(dt_bias);

    // 3) sequential scan -> ys (+ H_final)
    scan_kernel<<<B_SZ * NHEADS, 128>>>(H0, ys_p, Hout, writeH);

    // 4) output = ys @ W_out^T  [8192, 1024]  (tf32 MMA)
    {
        dim3 grid(DIM / 128, M_TOK / 128);
        gemm_tf32<<<grid, 256, 65536>>>(ys_p, wor_p, out, M_TOK, DIM, D_INNER);
    }
}

// round 5
// speedup vs baseline: 2.5613x; 1.2767x over previous
#include <cuda_runtime.h>
#include <cuda_bf16.h>
#include <cstdint>

#define DIM      1024
#define D_INNER  2048
#define NHEADS   16
#define HEADDIM  128
#define D_STATE  64
#define D_PROJ   4240   // 2*D_INNER + 2*D_STATE + NHEADS
#define B_SZ     8
#define T_SZ     1024
#define M_TOK    (B_SZ * T_SZ)   // 8192

// ---------------------------------------------------------------------------
// Scratch (no cudaMalloc allowed): device globals.
// ---------------------------------------------------------------------------
__device__ float g_ys[(size_t)M_TOK * D_INNER];           // 67 MB (tf32-rounded)
__device__ float g_xr[(size_t)M_TOK * DIM];               // 33 MB  x rounded
__device__ float g_wir[(size_t)D_PROJ * DIM];             // 17 MB  W_in rounded
__device__ float g_wor[(size_t)DIM * D_INNER];            // 8  MB  W_out rounded
__device__ float g_xst[(size_t)M_TOK * D_INNER];          // 67 MB  silu(x_p), [b,h,t,p]
__device__ float g_zt [(size_t)M_TOK * D_INNER];          // 67 MB  z, [b,h,t,p]
__device__ float g_Bc [(size_t)B_SZ * T_SZ * D_STATE];    // 2 MB   [bt,n]
__device__ float g_Cc [(size_t)B_SZ * T_SZ * D_STATE];    // 2 MB
__device__ float g_dec[(size_t)B_SZ * T_SZ * NHEADS];     // 0.5 MB sigmoid(dt+bias)

// ---------------------------------------------------------------------------
// helpers
// ---------------------------------------------------------------------------
__device__ __forceinline__ uint32_t f2tf32(float f) {
    uint32_t u;
    asm("cvt.rna.tf32.f32 %0, %1;" : "=r"(u) : "f"(f));
    return u;
}

__device__ __forceinline__ void cpasync16(uint32_t dst, const void* src) {
    asm volatile("cp.async.cg.shared.global [%0], [%1], 16;" :: "r"(dst), "l"(src));
}

__device__ __forceinline__ void mma_tf32(float* c, const uint32_t* a,
                                         uint32_t b0, uint32_t b1) {
    asm volatile(
        "mma.sync.aligned.m16n8k8.row.col.f32.tf32.tf32.f32 "
        "{%0,%1,%2,%3}, {%4,%5,%6,%7}, {%8,%9}, {%0,%1,%2,%3};"
        : "+f"(c[0]), "+f"(c[1]), "+f"(c[2]), "+f"(c[3])
        : "r"(a[0]), "r"(a[1]), "r"(a[2]), "r"(a[3]), "r"(b0), "r"(b1));
}

// ---------------------------------------------------------------------------
// round fp32 -> tf32-bits (stored as fp32)
// ---------------------------------------------------------------------------
__global__ void round_tf32(const float* __restrict__ src, float* __restrict__ dst, int n) {
    for (int i = blockIdx.x * blockDim.x + threadIdx.x; i < n;
         i += gridDim.x * blockDim.x)
        dst[i] = __uint_as_float(f2tf32(src[i]));
}

// ---------------------------------------------------------------------------
// scatter epilogue for GEMM1 (mode 1): route proj columns to scan-friendly
// buffers with activations. Pairs (col even, col+1) never cross a region
// boundary (all boundaries even).
// ---------------------------------------------------------------------------
__device__ __forceinline__ void scatter_pair(int row, int col, float v0, float v1,
                                             const float* __restrict__ dt_bias)
{
    const int b = row >> 10;
    const int t = row & 1023;
    if (col < D_INNER) {                        // x -> silu -> g_xst [b,h,t,p]
        const int h = col >> 7, pp = col & 127;
        const float s0 = v0 / (1.f + __expf(-v0));
        const float s1 = v1 / (1.f + __expf(-v1));
        *(float2*)(g_xst + ((size_t)(b * NHEADS + h) * T_SZ + t) * HEADDIM + pp)
            = make_float2(s0, s1);
    } else if (col < 2 * D_INNER) {             // z -> g_zt [b,h,t,p]
        const int c = col - D_INNER;
        const int h = c >> 7, pp = c & 127;
        *(float2*)(g_zt + ((size_t)(b * NHEADS + h) * T_SZ + t) * HEADDIM + pp)
            = make_float2(v0, v1);
    } else if (col < 2 * D_INNER + D_STATE) {   // B -> g_Bc [bt,n]
        *(float2*)(g_Bc + (size_t)row * D_STATE + (col - 2 * D_INNER))
            = make_float2(v0, v1);
    } else if (col < 2 * D_INNER + 2 * D_STATE) { // C -> g_Cc [bt,n]
        *(float2*)(g_Cc + (size_t)row * D_STATE + (col - 2 * D_INNER - D_STATE))
            = make_float2(v0, v1);
    } else {                                    // dt -> sigmoid(dt+bias) -> g_dec
        const int h = col - (2 * D_INNER + 2 * D_STATE);
        g_dec[(size_t)row * NHEADS + h]     = 1.f / (1.f + __expf(-(v0 + dt_bias[h])));
        g_dec[(size_t)row * NHEADS + h + 1] = 1.f / (1.f + __expf(-(v1 + dt_bias[h + 1])));
    }
}

// ---------------------------------------------------------------------------
// tf32 tensor-core GEMM, NT form: C[m,n] = sum_k A[m,k] * W[n,k]
// BM=BN=128, BK=32, 256 threads (8 warps), warp tile 64x32, 3-stage cp.async.
// mode 0: plain C write. mode 1: mamba scatter epilogue (C unused).
// ---------------------------------------------------------------------------
__global__ void __launch_bounds__(256, 2)
gemm_tf32(const float* __restrict__ A, const float* __restrict__ W,
          float* __restrict__ C, int M, int N, int K,
          int mode, const float* __restrict__ dt_bias)
{
    extern __shared__ float smem[];   // 3 stages x (A 4096 + B 4096) floats = 96KB
    const uint32_t smemAddr = (uint32_t)__cvta_generic_to_shared(smem);

    const int tid  = threadIdx.x;
    const int lane = tid & 31;
    const int wid  = tid >> 5;
    const int wm   = wid & 1;
    const int wn   = wid >> 1;

    const int bm = blockIdx.y * 128;
    const int bn = blockIdx.x * 128;

    const int sr   = tid >> 1;
    const int half = tid & 1;
    const float* arow = A + (size_t)(bm + sr) * K;
    const int wRow = (bn + sr) < N ? (bn + sr) : (N - 1);
    const float* wrow = W + (size_t)wRow * K;

    int cx[8];
#pragma unroll
    for (int j = 0; j < 8; j++)
        cx[j] = ((j ^ (lane >> 2)) << 2) + (lane & 3);
    int rA[4], rB[4];
#pragma unroll
    for (int mt = 0; mt < 4; mt++)
        rA[mt] = (wm * 64 + mt * 16 + (lane >> 2)) * 32;
#pragma unroll
    for (int nt = 0; nt < 4; nt++)
        rB[nt] = (wn * 32 + nt * 8 + (lane >> 2)) * 32;

    float acc[4][4][4];
#pragma unroll
    for (int mt = 0; mt < 4; mt++)
#pragma unroll
        for (int nt = 0; nt < 4; nt++)
#pragma unroll
            for (int r = 0; r < 4; r++) acc[mt][nt][r] = 0.f;

    const int nk = K >> 5;

#define STAGE(bufIdx, kk)                                                     \
    do {                                                                      \
        uint32_t baseA = smemAddr + (bufIdx) * 32768 + sr * 128;              \
        uint32_t baseB = baseA + 16384;                                       \
        _Pragma("unroll")                                                     \
        for (int i = 0; i < 4; i++) {                                         \
            int ch  = half * 4 + i;                                           \
            int chs = ch ^ (sr & 7);                                          \
            cpasync16(baseA + chs * 16, arow + (kk) + ch * 4);                \
            cpasync16(baseB + chs * 16, wrow + (kk) + ch * 4);                \
        }                                                                     \
    } while (0)

    STAGE(0, 0);
    asm volatile("cp.async.commit_group;");
    if (nk > 1) STAGE(1, 32);
    asm volatile("cp.async.commit_group;");

    int bufC = 0, bufP = 2;
    for (int kt = 0; kt < nk; kt++) {
        if (kt + 2 < nk) STAGE(bufP, (kt + 2) * 32);
        asm volatile("cp.async.commit_group;");      // unconditional: stable counts
        asm volatile("cp.async.wait_group 2;");
        __syncthreads();

        const uint32_t* sAu = reinterpret_cast<const uint32_t*>(smem) + bufC * 8192;
        const uint32_t* sBu = sAu + 4096;

#pragma unroll
        for (int ks = 0; ks < 4; ks++) {
            uint32_t bf[4][2];
#pragma unroll
            for (int nt = 0; nt < 4; nt++) {
                bf[nt][0] = sBu[rB[nt] + cx[2 * ks]];
                bf[nt][1] = sBu[rB[nt] + cx[2 * ks + 1]];
            }
            uint32_t af[4][4];
#pragma unroll
            for (int mt = 0; mt < 4; mt++) {
                af[mt][0] = sAu[rA[mt] + cx[2 * ks]];
                af[mt][1] = sAu[rA[mt] + 256 + cx[2 * ks]];
                af[mt][2] = sAu[rA[mt] + cx[2 * ks + 1]];
                af[mt][3] = sAu[rA[mt] + 256 + cx[2 * ks + 1]];
            }
#pragma unroll
            for (int mt = 0; mt < 4; mt++)
#pragma unroll
                for (int nt = 0; nt < 4; nt++)
                    mma_tf32(acc[mt][nt], af[mt], bf[nt][0], bf[nt][1]);
        }
        __syncthreads();
        bufC = (bufC == 2) ? 0 : bufC + 1;
        bufP = (bufP == 2) ? 0 : bufP + 1;
    }
#undef STAGE

#pragma unroll
    for (int mt = 0; mt < 4; mt++) {
        const int row0 = bm + wm * 64 + mt * 16 + (lane >> 2);
#pragma unroll
        for (int nt = 0; nt < 4; nt++) {
            const int col = bn + wn * 32 + nt * 8 + (lane & 3) * 2;
            if (col < N) {
                if (mode == 0) {
                    *(float2*)(C + (size_t)row0 * N + col)
                        = make_float2(acc[mt][nt][0], acc[mt][nt][1]);
                    *(float2*)(C + (size_t)(row0 + 8) * N + col)
                        = make_float2(acc[mt][nt][2], acc[mt][nt][3]);
                } else {
                    scatter_pair(row0,     col, acc[mt][nt][0], acc[mt][nt][1], dt_bias);
                    scatter_pair(row0 + 8, col, acc[mt][nt][2], acc[mt][nt][3], dt_bias);
                }
            }
        }
    }
}

// ---------------------------------------------------------------------------
// scan: one block per (b,h), 128 threads; thread p owns H[p,0:64] in regs.
// B/C: 8-deep smem ring fed by cp.async (commit/step, wait_group 6 -> 7-step
// latency cover; barriers do NOT drain cp.async). xs/z/dec: depth-4 register
// pipeline via 4x unroll (compile-time slot indices). One barrier per step,
// placed before the ring-slot overwrite.
// ---------------------------------------------------------------------------
__global__ void __launch_bounds__(128)
scan_kernel(const float* __restrict__ H0, float* __restrict__ ys,
            float* __restrict__ Hout, int writeH)
{
    const int bh = blockIdx.x;
    const int b  = bh >> 4;
    const int h  = bh & 15;
    const int p  = threadIdx.x;

    float H[64];
    const float* h0p = H0 + (((size_t)bh * HEADDIM) + p) * D_STATE;
#pragma unroll
    for (int n = 0; n < 64; n++) H[n] = h0p[n];

    const float* xsp  = g_xst + (size_t)bh * T_SZ * HEADDIM + p;
    const float* zp   = g_zt  + (size_t)bh * T_SZ * HEADDIM + p;
    const float* decp = g_dec + (size_t)b * T_SZ * NHEADS + h;
    const float* Bcb  = g_Bc + (size_t)b * T_SZ * D_STATE;
    const float* Ccb  = g_Cc + (size_t)b * T_SZ * D_STATE;

    __shared__ __align__(16) float sB[8][64];
    __shared__ __align__(16) float sC[8][64];
    const uint32_t sBaddr = (uint32_t)__cvta_generic_to_shared(sB);
    const uint32_t sCaddr = (uint32_t)__cvta_generic_to_shared(sC);

    // cp.async ring prologue: slots 0..6, one commit group each
#pragma unroll
    for (int s = 0; s < 7; s++) {
        if (p < 16)       cpasync16(sBaddr + s * 256 + p * 16,        Bcb + s * 64 + p * 4);
        else if (p < 32)  cpasync16(sCaddr + s * 256 + (p - 16) * 16, Ccb + s * 64 + (p - 16) * 4);
        asm volatile("cp.async.commit_group;");
    }

    // register pipeline depth 4
    float xs_p[4], z_p[4], d_p[4];
#pragma unroll
    for (int j = 0; j < 4; j++) {
        xs_p[j] = xsp[j * HEADDIM];
        z_p[j]  = zp[j * HEADDIM];
        d_p[j]  = decp[j * NHEADS];
    }

    float* ysp = ys + (size_t)(b * T_SZ) * D_INNER + h * HEADDIM + p;

    for (int t0 = 0; t0 < T_SZ; t0 += 4) {
#pragma unroll
        for (int j = 0; j < 4; j++) {
            const int t = t0 + j;

            // step t's data guaranteed in: allow 6 newest groups pending
            asm volatile("cp.async.wait_group 6;");
            __syncthreads();   // all threads done with slot (t-1)&7 and see slot t

            // prefetch step t+7 into ring slot (t+7)&7
            const int tp = t + 7;
            if (tp < T_SZ) {
                if (p < 16)
                    cpasync16(sBaddr + (tp & 7) * 256 + p * 16, Bcb + tp * 64 + p * 4);
                else if (p < 32)
                    cpasync16(sCaddr + (tp & 7) * 256 + (p - 16) * 16,
                              Ccb + tp * 64 + (p - 16) * 4);
            }
            asm volatile("cp.async.commit_group;");

            const float xs  = xs_p[j];
            const float zv  = z_p[j];
            const float dec = d_p[j];

            // refill register slot j with step t+4
            const int tf = t + 4;
            if (tf < T_SZ) {
                xs_p[j] = xsp[tf * HEADDIM];
                z_p[j]  = zp[tf * HEADDIM];
                d_p[j]  = decp[tf * NHEADS];
            }

            const float* Bc = sB[t & 7];
            const float* Cc = sC[t & 7];

            float y0 = 0.f, y1 = 0.f, y2 = 0.f, y3 = 0.f;
#pragma unroll
            for (int n = 0; n < 64; n += 8) {
                float4 bA = *(const float4*)&Bc[n];
                float4 bB = *(const float4*)&Bc[n + 4];
                float4 cA = *(const float4*)&Cc[n];
                float4 cB = *(const float4*)&Cc[n + 4];
                H[n + 0] = dec * H[n + 0] + xs * bA.x;  y0 += H[n + 0] * cA.x;
                H[n + 1] = dec * H[n + 1] + xs * bA.y;  y1 += H[n + 1] * cA.y;
                H[n + 2] = dec * H[n + 2] + xs * bA.z;  y2 += H[n + 2] * cA.z;
                H[n + 3] = dec * H[n + 3] + xs * bA.w;  y3 += H[n + 3] * cA.w;
                H[n + 4] = dec * H[n + 4] + xs * bB.x;  y0 += H[n + 4] * cB.x;
                H[n + 5] = dec * H[n + 5] + xs * bB.y;  y1 += H[n + 5] * cB.y;
                H[n + 6] = dec * H[n + 6] + xs * bB.z;  y2 += H[n + 6] * cB.z;
                H[n + 7] = dec * H[n + 7] + xs * bB.w;  y3 += H[n + 7] * cB.w;
            }
            const float y  = (y0 + y1) + (y2 + y3);
            const float zy = zv + y;
            const float ov = y * (zy / (1.f + __expf(-zy)));
            ysp[(size_t)t * D_INNER] = __uint_as_float(f2tf32(ov));
        }
    }

    if (writeH) {
        float* hp = Hout + (((size_t)bh * HEADDIM) + p) * D_STATE;
#pragma unroll
        for (int n = 0; n < 64; n++) hp[n] = H[n];
    }
}

// ---------------------------------------------------------------------------
extern "C" void kernel_launch(void* const* d_in, const int* in_sizes, int n_in,
                              void* d_out, int out_size)
{
    const float* x       = (const float*)d_in[0];
    const float* H0      = (const float*)d_in[1];
    const float* W_in    = (const float*)d_in[2];
    const float* W_out   = (const float*)d_in[3];
    const float* dt_bias = (const float*)d_in[4];
    float* out = (float*)d_out;

    static float *ys_p = nullptr, *xr_p = nullptr, *wir_p = nullptr, *wor_p = nullptr;
    if (!ys_p) {
        cudaGetSymbolAddress((void**)&ys_p,  g_ys);
        cudaGetSymbolAddress((void**)&xr_p,  g_xr);
        cudaGetSymbolAddress((void**)&wir_p, g_wir);
        cudaGetSymbolAddress((void**)&wor_p, g_wor);
        cudaFuncSetAttribute(gemm_tf32,
                             cudaFuncAttributeMaxDynamicSharedMemorySize, 98304);
    }

    const int out_elems = B_SZ * T_SZ * DIM;
    const int h_elems   = B_SZ * NHEADS * HEADDIM * D_STATE;
    const int writeH    = (out_size >= out_elems + h_elems) ? 1 : 0;
    float* Hout = out + out_elems;

    // 0) tf32-round GEMM inputs
    round_tf32<<<2048, 256>>>(x,     xr_p,  M_TOK * DIM);
    round_tf32<<<2048, 256>>>(W_in,  wir_p, D_PROJ * DIM);
    round_tf32<<<1024, 256>>>(W_out, wor_p, DIM * D_INNER);

    // 1) proj GEMM with fused scatter epilogue (silu/sigmoid/reshape)
    {
        dim3 grid((D_PROJ + 127) / 128, M_TOK / 128);
        gemm_tf32<<<grid, 256, 98304>>>(xr_p, wir_p, nullptr,
                                        M_TOK, D_PROJ, DIM, 1, dt_bias);
    }
    // 2) sequential scan -> ys (+ H_final)
    scan_kernel<<<B_SZ * NHEADS, 128>>>(H0, ys_p, Hout, writeH);

    // 3) output = ys @ W_out^T  [8192, 1024]
    {
        dim3 grid(DIM / 128, M_TOK / 128);
        gemm_tf32<<<grid, 256, 98304>>>(ys_p, wor_p, out,
                                        M_TOK, DIM, D_INNER, 0, nullptr);
    }
}

// round 6
// speedup vs baseline: 3.2370x; 1.2638x over previous
#include <cuda_runtime.h>
#include <cuda_bf16.h>
#include <cstdint>

#define DIM      1024
#define D_INNER  2048
#define NHEADS   16
#define HEADDIM  128
#define D_STATE  64
#define D_PROJ   4240   // 2*D_INNER + 2*D_STATE + NHEADS
#define B_SZ     8
#define T_SZ     1024
#define M_TOK    (B_SZ * T_SZ)   // 8192
#define NBH      (B_SZ * NHEADS) // 128
#define CHUNK    64
#define NCHUNK   (T_SZ / CHUNK)  // 16

// ---------------------------------------------------------------------------
// Scratch (no cudaMalloc allowed): device globals.
// ---------------------------------------------------------------------------
__device__ float g_ys[(size_t)M_TOK * D_INNER];            // 67 MB final gated ys (tf32)
__device__ float g_xr[(size_t)M_TOK * DIM];                // x tf32-rounded
__device__ float g_wir[(size_t)D_PROJ * DIM];              // W_in rounded
__device__ float g_wor[(size_t)DIM * D_INNER];             // W_out rounded
__device__ float g_xst[(size_t)NBH * T_SZ * HEADDIM];      // silu(x_p) [bh,t,p]
__device__ float g_zt [(size_t)NBH * T_SZ * HEADDIM];      // z [bh,t,p]
__device__ float g_Bc [(size_t)M_TOK * D_STATE];           // [bt,n]
__device__ float g_Cc [(size_t)M_TOK * D_STATE];           // [bt,n]
__device__ float g_ldec[(size_t)M_TOK * NHEADS];           // log(sigmoid(dt+bias)) [bt,h]
__device__ float g_yint[(size_t)NBH * T_SZ * HEADDIM];     // intra-chunk Y [bh,t,p]
__device__ float g_dH [(size_t)NBH * NCHUNK * HEADDIM * D_STATE]; // per-chunk state delta
__device__ float g_Hc [(size_t)NBH * NCHUNK * HEADDIM * D_STATE]; // state ENTERING chunk c
__device__ float g_lcum[(size_t)NBH * T_SZ];               // within-chunk log-decay cumsum

// ---------------------------------------------------------------------------
// helpers
// ---------------------------------------------------------------------------
__device__ __forceinline__ uint32_t f2tf32(float f) {
    uint32_t u;
    asm("cvt.rna.tf32.f32 %0, %1;" : "=r"(u) : "f"(f));
    return u;
}

__device__ __forceinline__ void cpasync16(uint32_t dst, const void* src) {
    asm volatile("cp.async.cg.shared.global [%0], [%1], 16;" :: "r"(dst), "l"(src));
}

__device__ __forceinline__ void mma_tf32(float* c, const uint32_t* a,
                                         uint32_t b0, uint32_t b1) {
    asm volatile(
        "mma.sync.aligned.m16n8k8.row.col.f32.tf32.tf32.f32 "
        "{%0,%1,%2,%3}, {%4,%5,%6,%7}, {%8,%9}, {%0,%1,%2,%3};"
        : "+f"(c[0]), "+f"(c[1]), "+f"(c[2]), "+f"(c[3])
        : "r"(a[0]), "r"(a[1]), "r"(a[2]), "r"(a[3]), "r"(b0), "r"(b1));
}

__global__ void round_tf32(const float* __restrict__ src, float* __restrict__ dst, int n) {
    for (int i = blockIdx.x * blockDim.x + threadIdx.x; i < n;
         i += gridDim.x * blockDim.x)
        dst[i] = __uint_as_float(f2tf32(src[i]));
}

// ---------------------------------------------------------------------------
// scatter epilogue for GEMM1 (mode 1): route proj columns to scan buffers.
// ---------------------------------------------------------------------------
__device__ __forceinline__ void scatter_pair(int row, int col, float v0, float v1,
                                             const float* __restrict__ dt_bias)
{
    const int b = row >> 10;
    const int t = row & 1023;
    if (col < D_INNER) {                        // x -> silu -> g_xst [bh,t,p]
        const int h = col >> 7, pp = col & 127;
        const float s0 = v0 / (1.f + __expf(-v0));
        const float s1 = v1 / (1.f + __expf(-v1));
        *(float2*)(g_xst + ((size_t)(b * NHEADS + h) * T_SZ + t) * HEADDIM + pp)
            = make_float2(s0, s1);
    } else if (col < 2 * D_INNER) {             // z -> g_zt [bh,t,p]
        const int c = col - D_INNER;
        const int h = c >> 7, pp = c & 127;
        *(float2*)(g_zt + ((size_t)(b * NHEADS + h) * T_SZ + t) * HEADDIM + pp)
            = make_float2(v0, v1);
    } else if (col < 2 * D_INNER + D_STATE) {   // B
        *(float2*)(g_Bc + (size_t)row * D_STATE + (col - 2 * D_INNER))
            = make_float2(v0, v1);
    } else if (col < 2 * D_INNER + 2 * D_STATE) { // C
        *(float2*)(g_Cc + (size_t)row * D_STATE + (col - 2 * D_INNER - D_STATE))
            = make_float2(v0, v1);
    } else {                                    // dt -> log(sigmoid(dt+bias))
        const int h = col - (2 * D_INNER + 2 * D_STATE);
        const float u0 = v0 + dt_bias[h];
        const float u1 = v1 + dt_bias[h + 1];
        g_ldec[(size_t)row * NHEADS + h]     = (u0 > -15.f) ? -log1pf(__expf(-u0)) : u0;
        g_ldec[(size_t)row * NHEADS + h + 1] = (u1 > -15.f) ? -log1pf(__expf(-u1)) : u1;
    }
}

// ---------------------------------------------------------------------------
// tf32 tensor-core GEMM, NT form (unchanged from R5)
// ---------------------------------------------------------------------------
__global__ void __launch_bounds__(256, 2)
gemm_tf32(const float* __restrict__ A, const float* __restrict__ W,
          float* __restrict__ C, int M, int N, int K,
          int mode, const float* __restrict__ dt_bias)
{
    extern __shared__ float smem[];
    const uint32_t smemAddr = (uint32_t)__cvta_generic_to_shared(smem);

    const int tid  = threadIdx.x;
    const int lane = tid & 31;
    const int wid  = tid >> 5;
    const int wm   = wid & 1;
    const int wn   = wid >> 1;

    const int bm = blockIdx.y * 128;
    const int bn = blockIdx.x * 128;

    const int sr   = tid >> 1;
    const int half = tid & 1;
    const float* arow = A + (size_t)(bm + sr) * K;
    const int wRow = (bn + sr) < N ? (bn + sr) : (N - 1);
    const float* wrow = W + (size_t)wRow * K;

    int cx[8];
#pragma unroll
    for (int j = 0; j < 8; j++)
        cx[j] = ((j ^ (lane >> 2)) << 2) + (lane & 3);
    int rA[4], rB[4];
#pragma unroll
    for (int mt = 0; mt < 4; mt++)
        rA[mt] = (wm * 64 + mt * 16 + (lane >> 2)) * 32;
#pragma unroll
    for (int nt = 0; nt < 4; nt++)
        rB[nt] = (wn * 32 + nt * 8 + (lane >> 2)) * 32;

    float acc[4][4][4];
#pragma unroll
    for (int mt = 0; mt < 4; mt++)
#pragma unroll
        for (int nt = 0; nt < 4; nt++)
#pragma unroll
            for (int r = 0; r < 4; r++) acc[mt][nt][r] = 0.f;

    const int nk = K >> 5;

#define STAGE(bufIdx, kk)                                                     \
    do {                                                                      \
        uint32_t baseA = smemAddr + (bufIdx) * 32768 + sr * 128;              \
        uint32_t baseB = baseA + 16384;                                       \
        _Pragma("unroll")                                                     \
        for (int i = 0; i < 4; i++) {                                         \
            int ch  = half * 4 + i;                                           \
            int chs = ch ^ (sr & 7);                                          \
            cpasync16(baseA + chs * 16, arow + (kk) + ch * 4);                \
            cpasync16(baseB + chs * 16, wrow + (kk) + ch * 4);                \
        }                                                                     \
    } while (0)

    STAGE(0, 0);
    asm volatile("cp.async.commit_group;");
    if (nk > 1) STAGE(1, 32);
    asm volatile("cp.async.commit_group;");

    int bufC = 0, bufP = 2;
    for (int kt = 0; kt < nk; kt++) {
        if (kt + 2 < nk) STAGE(bufP, (kt + 2) * 32);
        asm volatile("cp.async.commit_group;");
        asm volatile("cp.async.wait_group 2;");
        __syncthreads();

        const uint32_t* sAu = reinterpret_cast<const uint32_t*>(smem) + bufC * 8192;
        const uint32_t* sBu = sAu + 4096;

#pragma unroll
        for (int ks = 0; ks < 4; ks++) {
            uint32_t bf[4][2];
#pragma unroll
            for (int nt = 0; nt < 4; nt++) {
                bf[nt][0] = sBu[rB[nt] + cx[2 * ks]];
                bf[nt][1] = sBu[rB[nt] + cx[2 * ks + 1]];
            }
            uint32_t af[4][4];
#pragma unroll
            for (int mt = 0; mt < 4; mt++) {
                af[mt][0] = sAu[rA[mt] + cx[2 * ks]];
                af[mt][1] = sAu[rA[mt] + 256 + cx[2 * ks]];
                af[mt][2] = sAu[rA[mt] + cx[2 * ks + 1]];
                af[mt][3] = sAu[rA[mt] + 256 + cx[2 * ks + 1]];
            }
#pragma unroll
            for (int mt = 0; mt < 4; mt++)
#pragma unroll
                for (int nt = 0; nt < 4; nt++)
                    mma_tf32(acc[mt][nt], af[mt], bf[nt][0], bf[nt][1]);
        }
        __syncthreads();
        bufC = (bufC == 2) ? 0 : bufC + 1;
        bufP = (bufP == 2) ? 0 : bufP + 1;
    }
#undef STAGE

#pragma unroll
    for (int mt = 0; mt < 4; mt++) {
        const int row0 = bm + wm * 64 + mt * 16 + (lane >> 2);
#pragma unroll
        for (int nt = 0; nt < 4; nt++) {
            const int col = bn + wn * 32 + nt * 8 + (lane & 3) * 2;
            if (col < N) {
                if (mode == 0) {
                    *(float2*)(C + (size_t)row0 * N + col)
                        = make_float2(acc[mt][nt][0], acc[mt][nt][1]);
                    *(float2*)(C + (size_t)(row0 + 8) * N + col)
                        = make_float2(acc[mt][nt][2], acc[mt][nt][3]);
                } else {
                    scatter_pair(row0,     col, acc[mt][nt][0], acc[mt][nt][1], dt_bias);
                    scatter_pair(row0 + 8, col, acc[mt][nt][2], acc[mt][nt][3], dt_bias);
                }
            }
        }
    }
}

// ---------------------------------------------------------------------------
// Pass 1: intra-chunk (fully parallel). One block per (bh, chunk) = 2048.
//   Lcum = cumsum(log dec) within chunk
//   G[t,s] = (s<=t) ? exp(Lcum[t]-Lcum[s]) * (C_t . B_s) : 0
//   Y_intra = G @ Xs          (64x128)
//   dH[p,n] = sum_s exp(Lend-Lcum[s]) * xs_s[p] * B_s[n]
// ---------------------------------------------------------------------------
#define SB(s,n)  sB [(s) * 65 + (n)]
#define SC(s,n)  sC [(s) * 65 + (n)]
#define SG(t,s)  sG [(t) * 65 + (s)]

__global__ void __launch_bounds__(256)
chunk_intra()
{
    extern __shared__ float sm[];
    float* sXs = sm;                    // [64][128]
    float* sB  = sm + 8192;             // [64][65]
    float* sC  = sB + 4160;             // [64][65] (reused as decayed-B)
    float* sG  = sC + 4160;             // [64][65]
    float* sLc = sG + 4160;             // [64]
    float* sW  = sLc + 64;              // [64]

    const int blk = blockIdx.x;
    const int bh  = blk >> 4;
    const int c   = blk & 15;
    const int b   = bh >> 4;
    const int h   = bh & 15;
    const int tid = threadIdx.x;
    const int tx  = tid & 15;
    const int ty  = tid >> 4;

    const int tglob = b * T_SZ + c * CHUNK;             // [bt] base
    const size_t xbase = ((size_t)bh * T_SZ + c * CHUNK) * HEADDIM;

    // loads
    if (tid < 64)
        sLc[tid] = g_ldec[(size_t)(tglob + tid) * NHEADS + h];
    {
        const float4* src = (const float4*)(g_xst + xbase);
        for (int i = tid; i < 2048; i += 256) ((float4*)sXs)[i] = src[i];
    }
    for (int i = tid; i < 4096; i += 256) {
        const int s = i >> 6, n = i & 63;
        SB(s, n) = g_Bc[(size_t)(tglob + s) * D_STATE + n];
        SC(s, n) = g_Cc[(size_t)(tglob + s) * D_STATE + n];
    }
    __syncthreads();
    if (tid == 0) {
        float a = 0.f;
        for (int i = 0; i < 64; i++) { a += sLc[i]; sLc[i] = a; }
    }
    __syncthreads();

    // S & G: thread -> t rows [ty*4..+3], s cols [tx*4..+3]
    {
        float accS[4][4];
#pragma unroll
        for (int i = 0; i < 4; i++)
#pragma unroll
            for (int j = 0; j < 4; j++) accS[i][j] = 0.f;
        const int tS = ty * 4, sS = tx * 4;
        for (int n = 0; n < 64; n++) {
            float cr[4], br[4];
#pragma unroll
            for (int i = 0; i < 4; i++) cr[i] = SC(tS + i, n);
#pragma unroll
            for (int j = 0; j < 4; j++) br[j] = SB(sS + j, n);
#pragma unroll
            for (int i = 0; i < 4; i++)
#pragma unroll
                for (int j = 0; j < 4; j++) accS[i][j] += cr[i] * br[j];
        }
#pragma unroll
        for (int i = 0; i < 4; i++)
#pragma unroll
            for (int j = 0; j < 4; j++) {
                const int t = tS + i, s = sS + j;
                SG(t, s) = (s <= t) ? __expf(sLc[t] - sLc[s]) * accS[i][j] : 0.f;
            }
    }
    if (tid < 64) {
        sW[tid] = __expf(sLc[63] - sLc[tid]);
        g_lcum[(size_t)bh * T_SZ + c * CHUNK + tid] = sLc[tid];
    }
    __syncthreads();

    // decayed B into sC (overwrite; C no longer needed)
    for (int i = tid; i < 4096; i += 256) {
        const int s = i >> 6, n = i & 63;
        SC(s, n) = SB(s, n) * sW[s];
    }
    __syncthreads();

    // Y_intra: t rows [ty*4..+3], p cols [tx*8..+7]
    {
        float accY[4][8];
#pragma unroll
        for (int i = 0; i < 4; i++)
#pragma unroll
            for (int j = 0; j < 8; j++) accY[i][j] = 0.f;
        for (int s = 0; s < 64; s++) {
            float g[4];
#pragma unroll
            for (int i = 0; i < 4; i++) g[i] = SG(ty * 4 + i, s);
            float xv[8];
#pragma unroll
            for (int j = 0; j < 8; j++) xv[j] = sXs[s * 128 + tx * 8 + j];
#pragma unroll
            for (int i = 0; i < 4; i++)
#pragma unroll
                for (int j = 0; j < 8; j++) accY[i][j] += g[i] * xv[j];
        }
#pragma unroll
        for (int i = 0; i < 4; i++) {
            float* dst = g_yint + xbase + (size_t)(ty * 4 + i) * HEADDIM + tx * 8;
            *(float4*)(dst)     = make_float4(accY[i][0], accY[i][1], accY[i][2], accY[i][3]);
            *(float4*)(dst + 4) = make_float4(accY[i][4], accY[i][5], accY[i][6], accY[i][7]);
        }
    }

    // dH: p rows [ty*8..+7], n cols [tx*4..+3]
    {
        float accH[8][4];
#pragma unroll
        for (int i = 0; i < 8; i++)
#pragma unroll
            for (int j = 0; j < 4; j++) accH[i][j] = 0.f;
        for (int s = 0; s < 64; s++) {
            float xv[8];
#pragma unroll
            for (int i = 0; i < 8; i++) xv[i] = sXs[s * 128 + ty * 8 + i];
            float bw[4];
#pragma unroll
            for (int j = 0; j < 4; j++) bw[j] = SC(s, tx * 4 + j);
#pragma unroll
            for (int i = 0; i < 8; i++)
#pragma unroll
                for (int j = 0; j < 4; j++) accH[i][j] += xv[i] * bw[j];
        }
        const size_t hbase = ((size_t)(bh * NCHUNK + c)) * (HEADDIM * D_STATE);
#pragma unroll
        for (int i = 0; i < 8; i++) {
            float* dst = g_dH + hbase + (size_t)(ty * 8 + i) * D_STATE + tx * 4;
            *(float4*)dst = make_float4(accH[i][0], accH[i][1], accH[i][2], accH[i][3]);
        }
    }
}

// ---------------------------------------------------------------------------
// Pass 2: sequential chunk-state recurrence (128 blocks, tiny).
// g_Hc[bh][c] = state ENTERING chunk c. Final state -> Hout.
// ---------------------------------------------------------------------------
__global__ void __launch_bounds__(128)
chunk_state(const float* __restrict__ H0, float* __restrict__ Hout, int writeH)
{
    const int bh = blockIdx.x;
    const int p  = threadIdx.x;

    float H[64];
    const float4* h0p = (const float4*)(H0 + ((size_t)bh * HEADDIM + p) * D_STATE);
#pragma unroll
    for (int n = 0; n < 16; n++) ((float4*)H)[n] = h0p[n];

    for (int c = 0; c < NCHUNK; c++) {
        // store entering state
        float4* hc = (float4*)(g_Hc + ((size_t)(bh * NCHUNK + c)) * (HEADDIM * D_STATE)
                               + (size_t)p * D_STATE);
#pragma unroll
        for (int n = 0; n < 16; n++) hc[n] = ((float4*)H)[n];

        const float a = __expf(g_lcum[(size_t)bh * T_SZ + c * CHUNK + 63]);
        const float4* dh = (const float4*)(g_dH + ((size_t)(bh * NCHUNK + c)) * (HEADDIM * D_STATE)
                                           + (size_t)p * D_STATE);
#pragma unroll
        for (int n = 0; n < 16; n++) {
            float4 d = dh[n];
            float4* Hn = (float4*)H + n;
            Hn->x = a * Hn->x + d.x;
            Hn->y = a * Hn->y + d.y;
            Hn->z = a * Hn->z + d.z;
            Hn->w = a * Hn->w + d.w;
        }
    }

    if (writeH) {
        float4* hp = (float4*)(Hout + ((size_t)bh * HEADDIM + p) * D_STATE);
#pragma unroll
        for (int n = 0; n < 16; n++) hp[n] = ((float4*)H)[n];
    }
}

// ---------------------------------------------------------------------------
// Pass 3: inter-chunk Y + gate. One block per (bh, chunk) = 2048.
//   y = Y_intra + exp(Lcum[t]) * (C_t . H_enter)
//   out = y * silu(z + y) -> g_ys (tf32)
// ---------------------------------------------------------------------------
__global__ void __launch_bounds__(256)
chunk_inter(float* __restrict__ ys)
{
    extern __shared__ float sm[];
    float* sH  = sm;            // [128][65]
    float* sC3 = sm + 8320;     // [64][65]
    float* sP  = sC3 + 4160;    // [64]

    const int blk = blockIdx.x;
    const int bh  = blk >> 4;
    const int c   = blk & 15;
    const int b   = bh >> 4;
    const int h   = bh & 15;
    const int tid = threadIdx.x;
    const int tx  = tid & 15;   // -> t (4 rows)
    const int ty  = tid >> 4;   // -> p (8 rows)

    const int tglob = b * T_SZ + c * CHUNK;

    {
        const float* src = g_Hc + ((size_t)(bh * NCHUNK + c)) * (HEADDIM * D_STATE);
        for (int i = tid; i < 8192; i += 256) {
            const int p = i >> 6, n = i & 63;
            sH[p * 65 + n] = src[i];
        }
    }
    for (int i = tid; i < 4096; i += 256) {
        const int s = i >> 6, n = i & 63;
        sC3[s * 65 + n] = g_Cc[(size_t)(tglob + s) * D_STATE + n];
    }
    if (tid < 64)
        sP[tid] = __expf(g_lcum[(size_t)bh * T_SZ + c * CHUNK + tid]);
    __syncthreads();

    float acc[8][4];
#pragma unroll
    for (int i = 0; i < 8; i++)
#pragma unroll
        for (int j = 0; j < 4; j++) acc[i][j] = 0.f;

    for (int n = 0; n < 64; n++) {
        float hr[8];
#pragma unroll
        for (int i = 0; i < 8; i++) hr[i] = sH[(ty * 8 + i) * 65 + n];
        float cr[4];
#pragma unroll
        for (int j = 0; j < 4; j++) cr[j] = sC3[(tx * 4 + j) * 65 + n];
#pragma unroll
        for (int i = 0; i < 8; i++)
#pragma unroll
            for (int j = 0; j < 4; j++) acc[i][j] += hr[i] * cr[j];
    }

#pragma unroll
    for (int j = 0; j < 4; j++) {
        const int tl = tx * 4 + j;                          // 0..63 within chunk
        const size_t trow = (size_t)bh * T_SZ + c * CHUNK + tl;
        const float P = sP[tl];
        const float* yi = g_yint + trow * HEADDIM + ty * 8;
        const float* zz = g_zt   + trow * HEADDIM + ty * 8;
        float4 yi0 = *(const float4*)(yi);
        float4 yi1 = *(const float4*)(yi + 4);
        float4 z0  = *(const float4*)(zz);
        float4 z1  = *(const float4*)(zz + 4);
        float yv[8] = { yi0.x, yi0.y, yi0.z, yi0.w, yi1.x, yi1.y, yi1.z, yi1.w };
        float zv[8] = { z0.x, z0.y, z0.z, z0.w, z1.x, z1.y, z1.z, z1.w };
        uint32_t ov[8];
#pragma unroll
        for (int i = 0; i < 8; i++) {
            const float y  = yv[i] + P * acc[i][j];
            const float zy = zv[i] + y;
            ov[i] = f2tf32(y * (zy / (1.f + __expf(-zy))));
        }
        float* dst = ys + ((size_t)(b * T_SZ + c * CHUNK + tl)) * D_INNER
                        + h * HEADDIM + ty * 8;
        *(float4*)(dst) = make_float4(__uint_as_float(ov[0]), __uint_as_float(ov[1]),
                                      __uint_as_float(ov[2]), __uint_as_float(ov[3]));
        *(float4*)(dst + 4) = make_float4(__uint_as_float(ov[4]), __uint_as_float(ov[5]),
                                          __uint_as_float(ov[6]), __uint_as_float(ov[7]));
    }
}

// ---------------------------------------------------------------------------
extern "C" void kernel_launch(void* const* d_in, const int* in_sizes, int n_in,
                              void* d_out, int out_size)
{
    const float* x       = (const float*)d_in[0];
    const float* H0      = (const float*)d_in[1];
    const float* W_in    = (const float*)d_in[2];
    const float* W_out   = (const float*)d_in[3];
    const float* dt_bias = (const float*)d_in[4];
    float* out = (float*)d_out;

    static float *ys_p = nullptr, *xr_p = nullptr, *wir_p = nullptr, *wor_p = nullptr;
    if (!ys_p) {
        cudaGetSymbolAddress((void**)&ys_p,  g_ys);
        cudaGetSymbolAddress((void**)&xr_p,  g_xr);
        cudaGetSymbolAddress((void**)&wir_p, g_wir);
        cudaGetSymbolAddress((void**)&wor_p, g_wor);
        cudaFuncSetAttribute(gemm_tf32,
                             cudaFuncAttributeMaxDynamicSharedMemorySize, 98304);
        cudaFuncSetAttribute(chunk_intra,
                             cudaFuncAttributeMaxDynamicSharedMemorySize, 83456);
        cudaFuncSetAttribute(chunk_inter,
                             cudaFuncAttributeMaxDynamicSharedMemorySize, 50432);
    }

    const int out_elems = B_SZ * T_SZ * DIM;
    const int h_elems   = B_SZ * NHEADS * HEADDIM * D_STATE;
    const int writeH    = (out_size >= out_elems + h_elems) ? 1 : 0;
    float* Hout = out + out_elems;

    // 0) tf32-round GEMM inputs
    round_tf32<<<2048, 256>>>(x,     xr_p,  M_TOK * DIM);
    round_tf32<<<2048, 256>>>(W_in,  wir_p, D_PROJ * DIM);
    round_tf32<<<1024, 256>>>(W_out, wor_p, DIM * D_INNER);

    // 1) proj GEMM with fused scatter epilogue
    {
        dim3 grid((D_PROJ + 127) / 128, M_TOK / 128);
        gemm_tf32<<<grid, 256, 98304>>>(xr_p, wir_p, nullptr,
                                        M_TOK, D_PROJ, DIM, 1, dt_bias);
    }
    // 2) chunked scan
    chunk_intra<<<NBH * NCHUNK, 256, 83456>>>();
    chunk_state<<<NBH, 128>>>(H0, Hout, writeH);
    chunk_inter<<<NBH * NCHUNK, 256, 50432>>>(ys_p);

    // 3) output = ys @ W_out^T
    {
        dim3 grid(DIM / 128, M_TOK / 128);
        gemm_tf32<<<grid, 256, 98304>>>(ys_p, wor_p, out,
                                        M_TOK, DIM, D_INNER, 0, nullptr);
    }
}